// round 3
// baseline (speedup 1.0000x reference)
#include <cuda_runtime.h>
#include <cuda_fp16.h>
#include <cstdint>

#define USER_NUM 100000
#define N_NODES  200000
#define EMB      64
#define NNZ_MAX  4200000

#define SCAN_TPB 512
#define SCAN_BLOCKS ((N_NODES + SCAN_TPB - 1) / SCAN_TPB)   // 391

// ---- static device scratch (no allocation anywhere) ----
__device__ __half g_xh_a[(size_t)N_NODES * EMB];            // 25.6 MB fp16 gather buf
__device__ __half g_xh_b[(size_t)N_NODES * EMB];            // 25.6 MB fp16 gather buf
__device__ unsigned long long g_pairs[NNZ_MAX];             // 33.6 MB (val<<32 | col)
__device__ unsigned int g_cnt[N_NODES];
__device__ unsigned int g_rowptr[N_NODES + 1];
__device__ unsigned int g_rowcur[N_NODES];
__device__ unsigned int g_blocksum[SCAN_BLOCKS];
__device__ unsigned int g_is64;

// ---------------------------------------------------------------------------
// Zero histogram counters; block 0 also detects int64 vs int32 indices
// (high 32-bit words all zero over a sample => int64).
__global__ void init_kernel(const unsigned int* __restrict__ rows, int n_check) {
    int stride = gridDim.x * blockDim.x;
    for (int j = blockIdx.x * blockDim.x + threadIdx.x; j < N_NODES; j += stride)
        g_cnt[j] = 0u;
    if (blockIdx.x == 0) {
        __shared__ unsigned int s_acc;
        if (threadIdx.x == 0) s_acc = 0u;
        __syncthreads();
        unsigned int a = 0u;
        for (int j = threadIdx.x; j < n_check; j += blockDim.x)
            a |= rows[2 * j + 1];
        atomicOr(&s_acc, a);
        __syncthreads();
        if (threadIdx.x == 0) g_is64 = (s_acc == 0u) ? 1u : 0u;
    }
}

__device__ __forceinline__ int load_idx(const void* p, int e) {
    return g_is64 ? (int)((const long long*)p)[e] : ((const int*)p)[e];
}

// Convert f32 inputs (user ++ item) into the fp16 gather buffer.
__global__ void convert_kernel(const float2* __restrict__ user,
                               const float2* __restrict__ item,
                               __half2* __restrict__ xh) {
    const int nu = USER_NUM * EMB / 2;
    const int nt = N_NODES * EMB / 2;
    int stride = gridDim.x * blockDim.x;
    for (int i = blockIdx.x * blockDim.x + threadIdx.x; i < nt; i += stride) {
        float2 v = (i < nu) ? user[i] : item[i - nu];
        xh[i] = __floats2half2_rn(v.x, v.y);
    }
}

// ---------------------------------------------------------------------------
__global__ void hist_kernel(const void* __restrict__ rows, int nnz) {
    int e = blockIdx.x * blockDim.x + threadIdx.x;
    if (e >= nnz) return;
    atomicAdd(&g_cnt[load_idx(rows, e)], 1u);
}

// 3-phase exclusive scan of g_cnt into g_rowptr.
__global__ void scan1_kernel() {
    __shared__ unsigned int s[SCAN_TPB];
    int i = blockIdx.x * SCAN_TPB + threadIdx.x;
    unsigned int v = (i < N_NODES) ? g_cnt[i] : 0u;
    s[threadIdx.x] = v;
    __syncthreads();
    for (int off = 1; off < SCAN_TPB; off <<= 1) {
        unsigned int t = (threadIdx.x >= off) ? s[threadIdx.x - off] : 0u;
        __syncthreads();
        s[threadIdx.x] += t;
        __syncthreads();
    }
    unsigned int incl = s[threadIdx.x];
    if (i < N_NODES) g_rowptr[i] = incl - v;
    if (threadIdx.x == SCAN_TPB - 1) g_blocksum[blockIdx.x] = incl;
}

__global__ void scan2_kernel() {
    __shared__ unsigned int s[SCAN_TPB];
    unsigned int v = (threadIdx.x < SCAN_BLOCKS) ? g_blocksum[threadIdx.x] : 0u;
    s[threadIdx.x] = v;
    __syncthreads();
    for (int off = 1; off < SCAN_TPB; off <<= 1) {
        unsigned int t = (threadIdx.x >= off) ? s[threadIdx.x - off] : 0u;
        __syncthreads();
        s[threadIdx.x] += t;
        __syncthreads();
    }
    if (threadIdx.x < SCAN_BLOCKS) g_blocksum[threadIdx.x] = s[threadIdx.x] - v;
}

__global__ void scan3_kernel(int nnz) {
    int i = blockIdx.x * SCAN_TPB + threadIdx.x;
    if (i < N_NODES) {
        unsigned int p = g_rowptr[i] + g_blocksum[blockIdx.x];
        g_rowptr[i] = p;
        g_rowcur[i] = p;
    }
    if (i == 0) g_rowptr[N_NODES] = (unsigned int)nnz;
}

// Permute edges into row-sorted order as packed (val, col) 8-byte pairs.
__global__ void scatter_kernel(const void* __restrict__ rows,
                               const void* __restrict__ cols,
                               const float* __restrict__ val, int nnz) {
    int e = blockIdx.x * blockDim.x + threadIdx.x;
    if (e >= nnz) return;
    int r = load_idx(rows, e);
    int c = load_idx(cols, e);
    float v = __ldg(val + e);
    unsigned int pos = atomicAdd(&g_rowcur[r], 1u);
    g_pairs[pos] = ((unsigned long long)__float_as_uint(v) << 32) | (unsigned int)c;
}

// ---------------------------------------------------------------------------
// CSR SpMM with fp16 gather, f32 accumulation. One warp per row; two 16-lane
// halves process alternate edges with 2x unroll (4 gather streams in flight).
// Lane (half, sub) owns 4 consecutive half-elements (uint2) of the EMB=64 row.
// mode 0: out  = acc;       xh_next = fp16(acc)    (layer 1)
// mode 1: out += acc;       xh_next = fp16(acc)    (layer 2)
// mode 2: out  = (out+acc)/3                        (layer 3)
__global__ void spmm_csr_kernel(const __half* __restrict__ xh,
                                __half* __restrict__ xh_next,
                                float* __restrict__ out,
                                int mode) {
    int row = blockIdx.x * (blockDim.x >> 5) + (threadIdx.x >> 5);
    if (row >= N_NODES) return;
    int lane = threadIdx.x & 31;
    int half = lane >> 4;
    int sub  = lane & 15;

    unsigned int beg = g_rowptr[row];
    unsigned int end = g_rowptr[row + 1];

    float4 acc0 = make_float4(0.f, 0.f, 0.f, 0.f);
    float4 acc1 = make_float4(0.f, 0.f, 0.f, 0.f);

    const uint2* xh2 = (const uint2*)xh;   // uint2 = 4 halves; 16 per row

    unsigned int e = beg + half;
    while (e + 2 < end) {
        unsigned long long p0 = __ldcs(g_pairs + e);
        unsigned long long p1 = __ldcs(g_pairs + e + 2);
        int   c0 = (int)(unsigned int)p0;
        int   c1 = (int)(unsigned int)p1;
        float v0 = __uint_as_float((unsigned int)(p0 >> 32));
        float v1 = __uint_as_float((unsigned int)(p1 >> 32));
        uint2 h0 = __ldg(xh2 + (size_t)c0 * 16 + sub);
        uint2 h1 = __ldg(xh2 + (size_t)c1 * 16 + sub);
        float2 a0 = __half22float2(*(const __half2*)&h0.x);
        float2 b0 = __half22float2(*(const __half2*)&h0.y);
        float2 a1 = __half22float2(*(const __half2*)&h1.x);
        float2 b1 = __half22float2(*(const __half2*)&h1.y);
        acc0.x += v0 * a0.x; acc0.y += v0 * a0.y;
        acc0.z += v0 * b0.x; acc0.w += v0 * b0.y;
        acc1.x += v1 * a1.x; acc1.y += v1 * a1.y;
        acc1.z += v1 * b1.x; acc1.w += v1 * b1.y;
        e += 4;
    }
    if (e < end) {
        unsigned long long p0 = __ldcs(g_pairs + e);
        int   c0 = (int)(unsigned int)p0;
        float v0 = __uint_as_float((unsigned int)(p0 >> 32));
        uint2 h0 = __ldg(xh2 + (size_t)c0 * 16 + sub);
        float2 a0 = __half22float2(*(const __half2*)&h0.x);
        float2 b0 = __half22float2(*(const __half2*)&h0.y);
        acc0.x += v0 * a0.x; acc0.y += v0 * a0.y;
        acc0.z += v0 * b0.x; acc0.w += v0 * b0.y;
    }

    float4 acc;
    acc.x = acc0.x + acc1.x; acc.y = acc0.y + acc1.y;
    acc.z = acc0.z + acc1.z; acc.w = acc0.w + acc1.w;

    // combine the two halves (lane i += lane i^16)
    acc.x += __shfl_xor_sync(0xffffffffu, acc.x, 16);
    acc.y += __shfl_xor_sync(0xffffffffu, acc.y, 16);
    acc.z += __shfl_xor_sync(0xffffffffu, acc.z, 16);
    acc.w += __shfl_xor_sync(0xffffffffu, acc.w, 16);

    if (half == 0) {
        size_t o4 = (size_t)row * (EMB / 4) + sub;
        if (mode == 0) {
            ((float4*)out)[o4] = acc;
        } else if (mode == 1) {
            float4 t = ((float4*)out)[o4];
            t.x += acc.x; t.y += acc.y; t.z += acc.z; t.w += acc.w;
            ((float4*)out)[o4] = t;
        } else {
            const float s = 1.0f / 3.0f;
            float4 t = ((float4*)out)[o4];
            t.x = (t.x + acc.x) * s; t.y = (t.y + acc.y) * s;
            t.z = (t.z + acc.z) * s; t.w = (t.w + acc.w) * s;
            ((float4*)out)[o4] = t;
        }
        if (mode != 2) {
            uint2 ho;
            __half2 lo = __floats2half2_rn(acc.x, acc.y);
            __half2 hi = __floats2half2_rn(acc.z, acc.w);
            ho.x = *(const unsigned int*)&lo;
            ho.y = *(const unsigned int*)&hi;
            ((uint2*)xh_next)[(size_t)row * 16 + sub] = ho;
        }
    }
}

// ---------------------------------------------------------------------------
extern "C" void kernel_launch(void* const* d_in, const int* in_sizes, int n_in,
                              void* d_out, int out_size) {
    const float* user = (const float*)d_in[0];
    const float* item = (const float*)d_in[1];
    const void*  rows = d_in[2];
    const void*  cols = d_in[3];
    const float* val  = (const float*)d_in[4];
    int nnz = in_sizes[4];                 // adj_val count (dtype-independent)
    float* out = (float*)d_out;

    __half* xa = nullptr;
    __half* xb = nullptr;
    cudaGetSymbolAddress((void**)&xa, g_xh_a);
    cudaGetSymbolAddress((void**)&xb, g_xh_b);

    int n_check = 4096;
    if (nnz / 2 < n_check) n_check = nnz / 2;

    int eblocks = (nnz + 255) / 256;
    int rblocks = (N_NODES + 7) / 8;       // 8 warps (rows) per 256-thread block

    // Build CSR (reused by all 3 layers) + fp16 input conversion
    init_kernel<<<256, 256>>>((const unsigned int*)rows, n_check);
    hist_kernel<<<eblocks, 256>>>(rows, nnz);
    convert_kernel<<<1024, 256>>>((const float2*)user, (const float2*)item,
                                  (__half2*)xa);
    scan1_kernel<<<SCAN_BLOCKS, SCAN_TPB>>>();
    scan2_kernel<<<1, SCAN_TPB>>>();
    scan3_kernel<<<SCAN_BLOCKS, SCAN_TPB>>>(nnz);
    scatter_kernel<<<eblocks, 256>>>(rows, cols, val, nnz);

    // Layer 1: e1 = A x0; out = e1;  xh_b = fp16(e1)
    spmm_csr_kernel<<<rblocks, 256>>>(xa, xb, out, 0);
    // Layer 2: e2 = A e1; out += e2; xh_a = fp16(e2)
    spmm_csr_kernel<<<rblocks, 256>>>(xb, xa, out, 1);
    // Layer 3: e3 = A e2; out = (out + e3) / 3
    spmm_csr_kernel<<<rblocks, 256>>>(xa, nullptr, out, 2);
}